// round 1
// baseline (speedup 1.0000x reference)
#include <cuda_runtime.h>
#include <stdint.h>

// Problem constants (fixed by the dataset: B=4, H=376, W=1241, C=64, coords in [0,67))
#define BATCH   4
#define HH      376
#define WW      1241
#define CC      64
#define HW      (HH * WW)          // 466616
#define NUM_PIX (BATCH * HW)       // 1866464

// Scratch: packed (depth_bits<<32 | point_index) per pixel. ~14.9 MB.
__device__ unsigned long long g_keys[NUM_PIX];
// Projection matrix P = K @ R @ V2P (3x4, row-major)
__device__ float g_P[12];

// ---------------------------------------------------------------------------
// Kernel 1: init keys to sentinel; thread 0 computes the projection matrix.
// ---------------------------------------------------------------------------
__global__ void k_init(const float* __restrict__ K) {
    int t = blockIdx.x * blockDim.x + threadIdx.x;
    if (t == 0) {
        // KR = K @ R, where R = [[0,-1,0],[0,0,-1],[1,0,0]] (signed permutation)
        // (K@R)[i][0] = K[i][2]; (K@R)[i][1] = -K[i][0]; (K@R)[i][2] = -K[i][1]
        float KR[9];
        #pragma unroll
        for (int i = 0; i < 3; i++) {
            KR[i*3+0] =  K[i*3+2];
            KR[i*3+1] = -K[i*3+0];
            KR[i*3+2] = -K[i*3+1];
        }
        // V2P: diag(vx,vy,vz) with offsets; vx=vy=vz=0.75
        const float vv = 0.75f;
        const float xo = 0.375f;          // 0.75/2 + 0
        const float yo = -24.625f;        // 0.75/2 - 25
        const float zo = -24.625f;        // 0.75/2 - 25
        #pragma unroll
        for (int i = 0; i < 3; i++) {
            g_P[i*4+0] = KR[i*3+0] * vv;
            g_P[i*4+1] = KR[i*3+1] * vv;
            g_P[i*4+2] = KR[i*3+2] * vv;
            g_P[i*4+3] = KR[i*3+0]*xo + KR[i*3+1]*yo + KR[i*3+2]*zo;
        }
    }
    if (t < NUM_PIX) {
        g_keys[t] = 0xFFFFFFFFFFFFFFFFull;
    }
}

// ---------------------------------------------------------------------------
// Kernel 2: per-point projection + 64-bit packed atomicMin z-buffer.
// Packing (depth_bits<<32 | index) reproduces the reference's
// "min depth, then min index among ties" semantics in one atomic.
// ---------------------------------------------------------------------------
__global__ void k_scatter(const int* __restrict__ coords, int N) {
    int i = blockIdx.x * blockDim.x + threadIdx.x;
    if (i >= N) return;
    int4 c = reinterpret_cast<const int4*>(coords)[i];  // (b, z, y, x)
    float x = (float)c.w;
    float y = (float)c.z;
    float z = (float)c.y;

    float p0 = fmaf(g_P[0], x, fmaf(g_P[1], y, fmaf(g_P[2],  z, g_P[3])));
    float p1 = fmaf(g_P[4], x, fmaf(g_P[5], y, fmaf(g_P[6],  z, g_P[7])));
    float d  = fmaf(g_P[8], x, fmaf(g_P[9], y, fmaf(g_P[10], z, g_P[11])));

    if (d > 1e-6f) {
        // IEEE division so floor boundaries match the fp32 reference
        float uf = floorf(__fdiv_rn(p0, d));
        float vf = floorf(__fdiv_rn(p1, d));
        int u = (int)uf;
        int v = (int)vf;
        if (u >= 0 && u < WW && v >= 0 && v < HH) {
            int pix = c.x * HW + v * WW + u;
            unsigned long long key =
                ((unsigned long long)__float_as_uint(d) << 32) | (unsigned int)i;
            atomicMin(&g_keys[pix], key);
        }
    }
}

// ---------------------------------------------------------------------------
// Kernel 3: per-pixel gather. Thread t = linear pixel id (b, v, u with u
// fastest) -> consecutive threads write consecutive addresses in every
// channel plane (fully coalesced STG). Feature row read as float4 (L2 hits:
// the 51 MB feature array fits in L2).
// Output layout: [B*C*HW] features then [B*HW] inv_depth.
// ---------------------------------------------------------------------------
__global__ void k_gather(const float* __restrict__ feats, float* __restrict__ out) {
    int t = blockIdx.x * blockDim.x + threadIdx.x;
    if (t >= NUM_PIX) return;

    unsigned long long key = g_keys[t];
    int b = t / HW;
    int r = t - b * HW;

    float* op   = out + (size_t)b * CC * HW + r;
    float* invd = out + (size_t)NUM_PIX * CC;

    if (key == 0xFFFFFFFFFFFFFFFFull) {
        invd[t] = 0.0f;
        #pragma unroll
        for (int c = 0; c < CC; c++) {
            op[(size_t)c * HW] = 0.0f;
        }
    } else {
        float d = __uint_as_float((unsigned int)(key >> 32));
        invd[t] = __fdiv_rn(1.0f, d);
        unsigned int idx = (unsigned int)key;
        const float4* f = reinterpret_cast<const float4*>(feats + (size_t)idx * CC);
        #pragma unroll
        for (int q = 0; q < CC / 4; q++) {
            float4 v4 = __ldg(f + q);
            op[(size_t)(4*q + 0) * HW] = v4.x;
            op[(size_t)(4*q + 1) * HW] = v4.y;
            op[(size_t)(4*q + 2) * HW] = v4.z;
            op[(size_t)(4*q + 3) * HW] = v4.w;
        }
    }
}

// ---------------------------------------------------------------------------
extern "C" void kernel_launch(void* const* d_in, const int* in_sizes, int n_in,
                              void* d_out, int out_size) {
    const float* feats  = (const float*)d_in[0];   // (N, 64) f32
    const int*   coords = (const int*)d_in[1];     // (N, 4)  i32
    const float* K      = (const float*)d_in[2];   // (3, 3)  f32

    int N = in_sizes[0] / CC;
    float* out = (float*)d_out;

    const int T = 256;
    k_init<<<(NUM_PIX + T - 1) / T, T>>>(K);
    k_scatter<<<(N + T - 1) / T, T>>>(coords, N);
    k_gather<<<(NUM_PIX + T - 1) / T, T>>>(feats, out);
}